// round 3
// baseline (speedup 1.0000x reference)
#include <cuda_runtime.h>
#include <cuda_bf16.h>
#include <cstdint>

// GNNIntraAgg: out[b, :] = relu( mean_k features[neigh_ids[b,k], :] )
// B=16384, K=32, N=100000, D=256, fp32.
//
// R3: warp-per-batch-row; each lane owns a 32B (8-float) column slice.
// 256-bit gathers with L2::evict_last (pins the 102MB table in the 126MB L2),
// ids via shuffle broadcast (no smem), 256-bit streaming output stores.

namespace {
constexpr int K = 32;
constexpr int D = 256;
constexpr int ROWS_PER_BLOCK = 8;      // warps per block
constexpr int THREADS = ROWS_PER_BLOCK * 32;  // 256
}

struct F8 { float v[8]; };

__device__ __forceinline__ F8 ldg_256_evict_last(const float* p) {
    F8 r;
    uint32_t a0,a1,a2,a3,a4,a5,a6,a7;
    asm volatile("ld.global.nc.L2::evict_last.v8.b32 {%0,%1,%2,%3,%4,%5,%6,%7}, [%8];"
                 : "=r"(a0), "=r"(a1), "=r"(a2), "=r"(a3),
                   "=r"(a4), "=r"(a5), "=r"(a6), "=r"(a7)
                 : "l"(p));
    r.v[0]=__uint_as_float(a0); r.v[1]=__uint_as_float(a1);
    r.v[2]=__uint_as_float(a2); r.v[3]=__uint_as_float(a3);
    r.v[4]=__uint_as_float(a4); r.v[5]=__uint_as_float(a5);
    r.v[6]=__uint_as_float(a6); r.v[7]=__uint_as_float(a7);
    return r;
}

__device__ __forceinline__ void stg_256_streaming(float* p, const float* v) {
    asm volatile("st.global.cs.v8.b32 [%0], {%1,%2,%3,%4,%5,%6,%7,%8};"
                 :: "l"(p),
                    "r"(__float_as_uint(v[0])), "r"(__float_as_uint(v[1])),
                    "r"(__float_as_uint(v[2])), "r"(__float_as_uint(v[3])),
                    "r"(__float_as_uint(v[4])), "r"(__float_as_uint(v[5])),
                    "r"(__float_as_uint(v[6])), "r"(__float_as_uint(v[7]))
                 : "memory");
}

__global__ __launch_bounds__(THREADS)
void gnn_agg_kernel(const int* __restrict__ neigh_ids,
                    const float* __restrict__ features,
                    float* __restrict__ out,
                    int B)
{
    const int warp = threadIdx.x >> 5;
    const int lane = threadIdx.x & 31;
    const int b    = blockIdx.x * ROWS_PER_BLOCK + warp;
    if (b >= B) return;

    // Lane k holds neighbor id k for this batch row (coalesced, streaming).
    const int my_id = __ldcs(&neigh_ids[(size_t)b * K + lane]);

    float acc[8];
#pragma unroll
    for (int i = 0; i < 8; ++i) acc[i] = 0.f;

    const int col = lane * 8;          // this lane's float offset within D

#pragma unroll 8
    for (int k = 0; k < K; ++k) {
        const int row = __shfl_sync(0xFFFFFFFFu, my_id, k);
        const F8 v = ldg_256_evict_last(&features[(size_t)row * D + col]);
#pragma unroll
        for (int i = 0; i < 8; ++i) acc[i] += v.v[i];
    }

    const float s = 1.0f / (float)K;
#pragma unroll
    for (int i = 0; i < 8; ++i) acc[i] = fmaxf(acc[i] * s, 0.f);

    stg_256_streaming(&out[(size_t)b * D + col], acc);
}

extern "C" void kernel_launch(void* const* d_in, const int* in_sizes, int n_in,
                              void* d_out, int out_size)
{
    const int* neigh_ids   = (const int*)d_in[0];    // [B, K] int32
    const float* features  = (const float*)d_in[1];  // [N, D] fp32
    float* out             = (float*)d_out;          // [B, D] fp32

    const int B = in_sizes[0] / K;                   // 16384

    const int grid = (B + ROWS_PER_BLOCK - 1) / ROWS_PER_BLOCK;
    gnn_agg_kernel<<<grid, THREADS>>>(neigh_ids, features, out, B);
}